// round 1
// baseline (speedup 1.0000x reference)
#include <cuda_runtime.h>
#include <math.h>

#define BATCH 2
#define SEQ   2048
#define DIM   2048
#define NH    16
#define DH    128

// Scratch (134 MB total) — __device__ globals per allocation rules.
__device__ float g_Q[BATCH * SEQ * DIM];
__device__ float g_K[BATCH * SEQ * DIM];
__device__ float g_V[BATCH * SEQ * DIM];
__device__ float g_A[BATCH * SEQ * DIM];

// ---------------------------------------------------------------------------
// GEMM: C[M,N] = A[M,K] @ W[N,K]^T + bias[N]
// Both operands K-major (row-major A, row-major W) -> "NT" GEMM.
// 128x128 tile, BK=16, 256 threads, 8x8 per-thread micro-tile.
// ---------------------------------------------------------------------------
__global__ __launch_bounds__(256) void gemm_nt_kernel(
    const float* __restrict__ A, const float* __restrict__ W,
    const float* __restrict__ bias, float* __restrict__ C,
    int M, int N, int Kd)
{
    __shared__ float As[16][132];   // [k][m], padded to kill STS conflicts
    __shared__ float Bs[16][132];   // [k][n]

    const int tid = threadIdx.x;
    const int tx  = tid & 15;       // n dimension (16)
    const int ty  = tid >> 4;       // m dimension (16)
    const int bm  = blockIdx.y * 128;
    const int bn  = blockIdx.x * 128;

    float acc[8][8];
    #pragma unroll
    for (int i = 0; i < 8; i++)
        #pragma unroll
        for (int j = 0; j < 8; j++) acc[i][j] = 0.f;

    for (int k0 = 0; k0 < Kd; k0 += 16) {
        // Load tiles: 512 float4 each, 2 per thread, written transposed.
        #pragma unroll
        for (int p = 0; p < 2; p++) {
            int v   = tid + p * 256;         // 0..511
            int row = v >> 2;                // 0..127
            int k4  = (v & 3) * 4;           // 0,4,8,12
            float4 a = *(const float4*)&A[(size_t)(bm + row) * Kd + k0 + k4];
            As[k4 + 0][row] = a.x; As[k4 + 1][row] = a.y;
            As[k4 + 2][row] = a.z; As[k4 + 3][row] = a.w;
            float4 b = *(const float4*)&W[(size_t)(bn + row) * Kd + k0 + k4];
            Bs[k4 + 0][row] = b.x; Bs[k4 + 1][row] = b.y;
            Bs[k4 + 2][row] = b.z; Bs[k4 + 3][row] = b.w;
        }
        __syncthreads();

        #pragma unroll
        for (int kk = 0; kk < 16; kk++) {
            float a_f[8], b_f[8];
            *(float4*)&a_f[0] = *(const float4*)&As[kk][ty * 8];
            *(float4*)&a_f[4] = *(const float4*)&As[kk][ty * 8 + 4];
            *(float4*)&b_f[0] = *(const float4*)&Bs[kk][tx * 8];
            *(float4*)&b_f[4] = *(const float4*)&Bs[kk][tx * 8 + 4];
            #pragma unroll
            for (int i = 0; i < 8; i++)
                #pragma unroll
                for (int j = 0; j < 8; j++)
                    acc[i][j] += a_f[i] * b_f[j];
        }
        __syncthreads();
    }

    // Epilogue: add bias, store.
    float bj[8];
    #pragma unroll
    for (int j = 0; j < 8; j++) bj[j] = bias[bn + tx * 8 + j];

    #pragma unroll
    for (int i = 0; i < 8; i++) {
        int m = bm + ty * 8 + i;
        float4 o0, o1;
        o0.x = acc[i][0] + bj[0]; o0.y = acc[i][1] + bj[1];
        o0.z = acc[i][2] + bj[2]; o0.w = acc[i][3] + bj[3];
        o1.x = acc[i][4] + bj[4]; o1.y = acc[i][5] + bj[5];
        o1.z = acc[i][6] + bj[6]; o1.w = acc[i][7] + bj[7];
        float* crow = &C[(size_t)m * N + bn + tx * 8];
        *(float4*)&crow[0] = o0;
        *(float4*)&crow[4] = o1;
    }
}

// ---------------------------------------------------------------------------
// Flash attention (fp32, causal): one block = (b, h, 64-row q tile).
// Online softmax over 64-col K tiles. 256 threads, 16x16 grid.
// Scores micro-tile 4x4 per thread; AV micro-tile 4 rows x 8 cols.
// ---------------------------------------------------------------------------
#define FROWSTRIDE 132                     // 128 + 4 pad
#define FLASH_SMEM_FLOATS (3 * 64 * FROWSTRIDE + 64 * 64 + 3 * 64)
#define FLASH_SMEM_BYTES  (FLASH_SMEM_FLOATS * 4)

__global__ __launch_bounds__(256) void flash_kernel(
    const float* __restrict__ Q, const float* __restrict__ K,
    const float* __restrict__ V, const int* __restrict__ causal_ptr,
    float* __restrict__ O)
{
    extern __shared__ float sm[];
    float* Qs   = sm;                                 // [64][132]
    float* Ks   = Qs + 64 * FROWSTRIDE;               // [64][132]
    float* Vs   = Ks + 64 * FROWSTRIDE;               // [64][132]
    float* Ps   = Vs + 64 * FROWSTRIDE;               // [64][64]
    float* mrow = Ps + 64 * 64;                       // [64]
    float* lrow = mrow + 64;                          // [64]
    float* crow = lrow + 64;                          // [64]

    const int tid = threadIdx.x;
    const int tx  = tid & 15;                         // k-col / d-col dim
    const int ty  = tid >> 4;                         // q-row dim
    const int qt  = blockIdx.x;
    const int h   = blockIdx.y;
    const int b   = blockIdx.z;
    const int q0  = qt * 64;
    const size_t base = (size_t)b * SEQ * DIM + (size_t)h * DH;
    const int causal = *causal_ptr;
    const float scale = 0.08838834764831845f;         // 1/sqrt(128)

    // Load Q tile (row-major, coalesced).
    #pragma unroll
    for (int p = 0; p < 8; p++) {
        int i  = (tid >> 5) + p * 8;                  // row 0..63
        int d4 = (tid & 31) * 4;                      // col 0..124
        *(float4*)&Qs[i * FROWSTRIDE + d4] =
            *(const float4*)&Q[base + (size_t)(q0 + i) * DIM + d4];
    }
    if (tid < 64) { mrow[tid] = -INFINITY; lrow[tid] = 0.f; }

    float acc[4][8];
    #pragma unroll
    for (int r = 0; r < 4; r++)
        #pragma unroll
        for (int c = 0; c < 8; c++) acc[r][c] = 0.f;

    const int nkt = causal ? (qt + 1) : (SEQ / 64);

    for (int kt = 0; kt < nkt; kt++) {
        const int k0 = kt * 64;
        __syncthreads();   // prior AV reads of Ks/Vs/Ps done; Q/m/l init visible

        // Load K & V tiles.
        #pragma unroll
        for (int p = 0; p < 8; p++) {
            int i  = (tid >> 5) + p * 8;
            int d4 = (tid & 31) * 4;
            *(float4*)&Ks[i * FROWSTRIDE + d4] =
                *(const float4*)&K[base + (size_t)(k0 + i) * DIM + d4];
            *(float4*)&Vs[i * FROWSTRIDE + d4] =
                *(const float4*)&V[base + (size_t)(k0 + i) * DIM + d4];
        }
        __syncthreads();

        // Scores: c[r][s] = Q[q0+ty*4+r] . K[k0+tx*4+s]
        float cs[4][4];
        #pragma unroll
        for (int r = 0; r < 4; r++)
            #pragma unroll
            for (int s = 0; s < 4; s++) cs[r][s] = 0.f;

        #pragma unroll 4
        for (int d0 = 0; d0 < DH; d0 += 4) {
            float4 q4[4], k4[4];
            #pragma unroll
            for (int r = 0; r < 4; r++)
                q4[r] = *(const float4*)&Qs[(ty * 4 + r) * FROWSTRIDE + d0];
            #pragma unroll
            for (int s = 0; s < 4; s++)
                k4[s] = *(const float4*)&Ks[(tx * 4 + s) * FROWSTRIDE + d0];
            #pragma unroll
            for (int r = 0; r < 4; r++)
                #pragma unroll
                for (int s = 0; s < 4; s++)
                    cs[r][s] += q4[r].x * k4[s].x + q4[r].y * k4[s].y
                              + q4[r].z * k4[s].z + q4[r].w * k4[s].w;
        }

        // Scale + causal mask -> Ps
        #pragma unroll
        for (int r = 0; r < 4; r++) {
            int gq = q0 + ty * 4 + r;
            float4 o;
            float v0 = cs[r][0] * scale, v1 = cs[r][1] * scale;
            float v2 = cs[r][2] * scale, v3 = cs[r][3] * scale;
            int gk = k0 + tx * 4;
            o.x = (causal && (gk + 0) > gq) ? -INFINITY : v0;
            o.y = (causal && (gk + 1) > gq) ? -INFINITY : v1;
            o.z = (causal && (gk + 2) > gq) ? -INFINITY : v2;
            o.w = (causal && (gk + 3) > gq) ? -INFINITY : v3;
            *(float4*)&Ps[(ty * 4 + r) * 64 + tx * 4] = o;
        }
        __syncthreads();

        // Online softmax: one thread per row.
        if (tid < 64) {
            float m_old = mrow[tid];
            float mx = m_old;
            float* row = &Ps[tid * 64];
            #pragma unroll 8
            for (int c = 0; c < 64; c++) mx = fmaxf(mx, row[c]);
            float corr = __expf(m_old - mx);
            float s = 0.f;
            #pragma unroll 8
            for (int c = 0; c < 64; c++) {
                float e = __expf(row[c] - mx);
                row[c] = e;
                s += e;
            }
            lrow[tid] = lrow[tid] * corr + s;
            mrow[tid] = mx;
            crow[tid] = corr;
        }
        __syncthreads();

        // Rescale accumulators, then AV accumulate.
        float cr[4];
        #pragma unroll
        for (int r = 0; r < 4; r++) cr[r] = crow[ty * 4 + r];
        #pragma unroll
        for (int r = 0; r < 4; r++)
            #pragma unroll
            for (int c = 0; c < 8; c++) acc[r][c] *= cr[r];

        #pragma unroll 4
        for (int kk = 0; kk < 64; kk++) {
            float pr[4];
            #pragma unroll
            for (int r = 0; r < 4; r++)
                pr[r] = Ps[(ty * 4 + r) * 64 + kk];
            float4 v0 = *(const float4*)&Vs[kk * FROWSTRIDE + tx * 8];
            float4 v1 = *(const float4*)&Vs[kk * FROWSTRIDE + tx * 8 + 4];
            #pragma unroll
            for (int r = 0; r < 4; r++) {
                acc[r][0] += pr[r] * v0.x; acc[r][1] += pr[r] * v0.y;
                acc[r][2] += pr[r] * v0.z; acc[r][3] += pr[r] * v0.w;
                acc[r][4] += pr[r] * v1.x; acc[r][5] += pr[r] * v1.y;
                acc[r][6] += pr[r] * v1.z; acc[r][7] += pr[r] * v1.w;
            }
        }
    }

    // Epilogue: divide by l, store to [b, s, h*DH + d] layout.
    #pragma unroll
    for (int r = 0; r < 4; r++) {
        int i = ty * 4 + r;
        float inv = 1.f / lrow[i];
        float4 o0, o1;
        o0.x = acc[r][0] * inv; o0.y = acc[r][1] * inv;
        o0.z = acc[r][2] * inv; o0.w = acc[r][3] * inv;
        o1.x = acc[r][4] * inv; o1.y = acc[r][5] * inv;
        o1.z = acc[r][6] * inv; o1.w = acc[r][7] * inv;
        float* orow = &O[base + (size_t)(q0 + i) * DIM + tx * 8];
        *(float4*)&orow[0] = o0;
        *(float4*)&orow[4] = o1;
    }
}

// ---------------------------------------------------------------------------
extern "C" void kernel_launch(void* const* d_in, const int* in_sizes, int n_in,
                              void* d_out, int out_size)
{
    const float* q      = (const float*)d_in[0];
    const float* k      = (const float*)d_in[1];
    const float* v      = (const float*)d_in[2];
    const float* Wq     = (const float*)d_in[3];
    const float* bq     = (const float*)d_in[4];
    const float* Wk     = (const float*)d_in[5];
    const float* bk     = (const float*)d_in[6];
    const float* Wv     = (const float*)d_in[7];
    const float* bv     = (const float*)d_in[8];
    const float* Wo     = (const float*)d_in[9];
    const float* bo     = (const float*)d_in[10];
    const int*   causal = (const int*)d_in[11];
    float* out = (float*)d_out;

    float *Qb, *Kb, *Vb, *Ab;
    cudaGetSymbolAddress((void**)&Qb, g_Q);
    cudaGetSymbolAddress((void**)&Kb, g_K);
    cudaGetSymbolAddress((void**)&Vb, g_V);
    cudaGetSymbolAddress((void**)&Ab, g_A);

    const int M = BATCH * SEQ;                   // 4096
    dim3 ggrid(DIM / 128, M / 128);              // (16, 32)

    gemm_nt_kernel<<<ggrid, 256>>>(q, Wq, bq, Qb, M, DIM, DIM);
    gemm_nt_kernel<<<ggrid, 256>>>(k, Wk, bk, Kb, M, DIM, DIM);
    gemm_nt_kernel<<<ggrid, 256>>>(v, Wv, bv, Vb, M, DIM, DIM);

    cudaFuncSetAttribute(flash_kernel,
                         cudaFuncAttributeMaxDynamicSharedMemorySize,
                         FLASH_SMEM_BYTES);
    dim3 fgrid(SEQ / 64, NH, BATCH);             // (32, 16, 2)
    flash_kernel<<<fgrid, 256, FLASH_SMEM_BYTES>>>(Qb, Kb, Vb, causal, Ab);

    gemm_nt_kernel<<<ggrid, 256>>>(Ab, Wo, bo, out, M, DIM, DIM);
}